// round 3
// baseline (speedup 1.0000x reference)
#include <cuda_runtime.h>
#include <cuda_bf16.h>

#define TAGS 128
#define NTHREADS 256      // 2 lanes per tag: K split into two 64-halves
#define COPYB 132         // float index of duplicated p copy (528B offset -> disjoint banks)

// Packed f32x2 FMA/ADD (Blackwell).
__device__ __forceinline__ void fma2(double &acc, double a, double b) {
    asm("fma.rn.f32x2 %0, %1, %2, %0;" : "+d"(acc) : "d"(a), "d"(b));
}
__device__ __forceinline__ double add2(double a, double b) {
    double d;
    asm("add.rn.f32x2 %0, %1, %2;" : "=d"(d) : "d"(a), "d"(b));
    return d;
}

__global__ void __launch_bounds__(NTHREADS, 1) crf_logz_kernel(
    const float* __restrict__ emissions,     // [B, T, 1, TAGS]
    const int*   __restrict__ token_sizes,   // [B]
    const float* __restrict__ transitions,   // [1, 1, TAGS, TAGS]
    const float* __restrict__ head_t,        // [1, 1, TAGS]
    const float* __restrict__ last_t,        // [1, 1, TAGS]
    float*       __restrict__ out,           // [B, 1]
    int T)
{
    // Each p buffer holds TWO copies of p[128]: copy A at [0..127] for the
    // chunk-0 readers, copy B at [COPYB..COPYB+127] for the chunk-1 readers.
    // chunk0 LDS.128 hits banks 4j..4j+3; chunk1 (reading floats 196+4j)
    // hits banks 4j+4..4j+7 -> conflict-free wavefronts.
    __shared__ __align__(16) float pbuf[2][COPYB + TAGS];
    __shared__ float red[TAGS];

    const int s   = threadIdx.x;
    const int tag = s >> 1;          // output tag owned by this lane pair
    const int c   = s & 1;           // K-half: c=0 -> m in [0,64), c=1 -> [64,128)
    const int b   = blockIdx.x;
    const int len = token_sizes[b];
    const float* emb = emissions + (size_t)b * T * TAGS;

    // exp(transitions) for my K-half of column `tag`: 32 f32x2 register pairs.
    double T2[32];
#pragma unroll
    for (int i = 0; i < 32; ++i) {
        int m = c * 64 + 2 * i;
        float2 f;
        f.x = __expf(transitions[(m    ) * TAGS + tag]);
        f.y = __expf(transitions[(m + 1) * TAGS + tag]);
        T2[i] = *reinterpret_cast<double*>(&f);
    }

    // alpha_0 = head + emissions[0]  ->  p = exp(alpha)
    if (c == 0) {
        float v = __expf(head_t[tag] + emb[tag]);
        pbuf[0][tag]         = v;
        pbuf[0][COPYB + tag] = v;
    }
    int etot = 0;        // exact integer sum of stripped binary exponents
    int cur  = 0;
    const int rdoff = c ? (COPYB + 64) : 0;   // my K-half read base (float idx)

    // One recurrence step. E = exp(emission[t][tag]) precomputed off-chain.
    auto dostep = [&](float E) {
        __syncthreads();
        const float* pc = pbuf[cur];
        float c0 = pc[0];                                  // broadcast scalar
        int   e  = ((__float_as_int(c0) >> 23) & 255) - 127;
        float Es = E * __int_as_float((127 - e) << 23);    // E * 2^{-e}

        const double2* pd = reinterpret_cast<const double2*>(pc + rdoff);
        double a0 = 0.0, a1 = 0.0, a2 = 0.0, a3 = 0.0;
#pragma unroll
        for (int j = 0; j < 4; ++j) {
            double2 u = pd[4 * j    ];
            double2 v = pd[4 * j + 1];
            double2 w = pd[4 * j + 2];
            double2 x = pd[4 * j + 3];
            fma2(a0, u.x, T2[8 * j    ]);
            fma2(a1, u.y, T2[8 * j + 1]);
            fma2(a2, v.x, T2[8 * j + 2]);
            fma2(a3, v.y, T2[8 * j + 3]);
            fma2(a0, w.x, T2[8 * j + 4]);
            fma2(a1, w.y, T2[8 * j + 5]);
            fma2(a2, x.x, T2[8 * j + 6]);
            fma2(a3, x.y, T2[8 * j + 7]);
        }
        double s2 = add2(add2(a0, a1), add2(a2, a3));
        float2 sf = *reinterpret_cast<float2*>(&s2);
        float part = sf.x + sf.y;                 // my K-half partial
        part += __shfl_xor_sync(0xffffffffu, part, 1);   // combine halves

        float pn = part * Es;
        if (c == 0) {
            pbuf[cur ^ 1][tag]         = pn;
            pbuf[cur ^ 1][COPYB + tag] = pn;
        }
        etot += e;
        cur ^= 1;
    };

    // Main loop, unrolled x4; emissions exp()'d 4 steps (~900 cyc) ahead.
    int t = 1;
    float E0 = __expf(emb[((1 < T) ? 1 : T - 1) * TAGS + tag]);
    float E1 = __expf(emb[((2 < T) ? 2 : T - 1) * TAGS + tag]);
    float E2 = __expf(emb[((3 < T) ? 3 : T - 1) * TAGS + tag]);
    float E3 = __expf(emb[((4 < T) ? 4 : T - 1) * TAGS + tag]);

    for (; t + 4 <= len; t += 4) {
        int tp = t + 4;
        int i0 = (tp     < T) ? tp     : T - 1;
        int i1 = (tp + 1 < T) ? tp + 1 : T - 1;
        int i2 = (tp + 2 < T) ? tp + 2 : T - 1;
        int i3 = (tp + 3 < T) ? tp + 3 : T - 1;
        float G0 = __expf(emb[i0 * TAGS + tag]);
        float G1 = __expf(emb[i1 * TAGS + tag]);
        float G2 = __expf(emb[i2 * TAGS + tag]);
        float G3 = __expf(emb[i3 * TAGS + tag]);
        dostep(E0);
        dostep(E1);
        dostep(E2);
        dostep(E3);
        E0 = G0; E1 = G1; E2 = G2; E3 = G3;
    }
    if (t < len) { dostep(E0); ++t; }
    if (t < len) { dostep(E1); ++t; }
    if (t < len) { dostep(E2); ++t; }

    // Finalize: out[b] = etot*ln2 + log( sum_n p[n] * exp(last[n]) )
    __syncthreads();
    if (c == 0) red[tag] = pbuf[cur][tag] * __expf(last_t[tag]);
    __syncthreads();
#pragma unroll
    for (int sft = TAGS / 2; sft > 0; sft >>= 1) {
        if (s < sft) red[s] += red[s + sft];
        __syncthreads();
    }
    if (s == 0)
        out[b] = (float)((double)etot * 0.6931471805599453 +
                         (double)__logf(red[0]));
}

extern "C" void kernel_launch(void* const* d_in, const int* in_sizes, int n_in,
                              void* d_out, int out_size) {
    const float* em = (const float*)d_in[0];
    const int*   ts = (const int*)  d_in[1];
    const float* tr = (const float*)d_in[2];
    const float* hd = (const float*)d_in[3];
    const float* lt = (const float*)d_in[4];
    float* out = (float*)d_out;

    int B = in_sizes[1];                       // token_sizes count
    int T = in_sizes[0] / (B * TAGS);          // C == 1

    crf_logz_kernel<<<B, NTHREADS>>>(em, ts, tr, hd, lt, out, T);
}

// round 4
// speedup vs baseline: 1.3044x; 1.3044x over previous
#include <cuda_runtime.h>
#include <cuda_bf16.h>

#define TAGS 128

// Packed f32x2 FMA/ADD (Blackwell sm_103a).
__device__ __forceinline__ void fma2(double &acc, double a, double b) {
    asm("fma.rn.f32x2 %0, %1, %2, %0;" : "+d"(acc) : "d"(a), "d"(b));
}
__device__ __forceinline__ double add2(double a, double b) {
    double d;
    asm("add.rn.f32x2 %0, %1, %2;" : "=d"(d) : "d"(a), "d"(b));
    return d;
}

__global__ void __launch_bounds__(TAGS, 1) crf_logz_kernel(
    const float* __restrict__ emissions,     // [B, T, 1, TAGS]
    const int*   __restrict__ token_sizes,   // [B]
    const float* __restrict__ transitions,   // [1, 1, TAGS, TAGS]
    const float* __restrict__ head_t,        // [1, 1, TAGS]
    const float* __restrict__ last_t,        // [1, 1, TAGS]
    float*       __restrict__ out,           // [B, 1]
    int T)
{
    __shared__ __align__(16) float pbuf[2][TAGS];
    __shared__ float wsum[4];

    const int n = threadIdx.x;      // output tag owned by this thread
    const int b = blockIdx.x;       // batch element owned by this CTA
    const int len = token_sizes[b];
    const float* emb = emissions + (size_t)b * T * TAGS;

    // exp(transitions) column n, packed into f32x2 register pairs.
    double T2[TAGS / 2];
#pragma unroll
    for (int i = 0; i < TAGS / 2; ++i) {
        float2 f;
        f.x = __expf(transitions[(2 * i    ) * TAGS + n]);
        f.y = __expf(transitions[(2 * i + 1) * TAGS + n]);
        T2[i] = *reinterpret_cast<double*>(&f);
    }

    // alpha_0 = head + emissions[0]  ->  p = exp(alpha)
    pbuf[0][n] = __expf(head_t[n] + emb[n]);
    int etot = 0;        // exact integer sum of stripped binary exponents
    int fb = 0;          // which buffer holds the live p (tail bookkeeping)

// One recurrence step, SRC/DST compile-time (static smem addressing).
// RS: strip p[0]'s binary exponent (done once per 4-step group; growth
// between rescales is <= ~64 bits, safely inside fp32 range).
#define STEP(SRC, DST, EV, RS) do {                                        \
    __syncthreads();                                                       \
    float _Es; int _e;                                                     \
    if (RS) {                                                              \
        float _c0 = pbuf[SRC][0];                                          \
        _e  = ((__float_as_int(_c0) >> 23) & 255) - 127;                   \
        _Es = (EV) * __int_as_float((127 - _e) << 23);                     \
    } else { _e = 0; _Es = (EV); }                                         \
    const double2* _pd = reinterpret_cast<const double2*>(pbuf[SRC]);      \
    double _a0 = 0.0, _a1 = 0.0, _a2 = 0.0, _a3 = 0.0;                     \
    _Pragma("unroll")                                                      \
    for (int _i = 0; _i < 16; ++_i) {                                      \
        double2 _u = _pd[2 * _i];                                          \
        double2 _w = _pd[2 * _i + 1];                                      \
        fma2(_a0, _u.x, T2[4 * _i    ]);                                   \
        fma2(_a1, _u.y, T2[4 * _i + 1]);                                   \
        fma2(_a2, _w.x, T2[4 * _i + 2]);                                   \
        fma2(_a3, _w.y, T2[4 * _i + 3]);                                   \
    }                                                                      \
    double _s2 = add2(add2(_a0, _a1), add2(_a2, _a3));                     \
    float2 _sf = *reinterpret_cast<float2*>(&_s2);                         \
    pbuf[DST][n] = (_sf.x + _sf.y) * _Es;                                  \
    etot += _e;                                                            \
} while (0)

    // Main loop, groups of 4 steps (buffer returns to 0 each group).
    // Emissions are exp()'d 4 steps (~900 cyc) ahead of use.
    int t = 1;
    float E0 = __expf(emb[((1 < T) ? 1 : T - 1) * TAGS + n]);
    float E1 = __expf(emb[((2 < T) ? 2 : T - 1) * TAGS + n]);
    float E2 = __expf(emb[((3 < T) ? 3 : T - 1) * TAGS + n]);
    float E3 = __expf(emb[((4 < T) ? 4 : T - 1) * TAGS + n]);

    for (; t + 4 <= len; t += 4) {
        int tp = t + 4;
        int i0 = (tp     < T) ? tp     : T - 1;
        int i1 = (tp + 1 < T) ? tp + 1 : T - 1;
        int i2 = (tp + 2 < T) ? tp + 2 : T - 1;
        int i3 = (tp + 3 < T) ? tp + 3 : T - 1;
        float G0 = __expf(emb[i0 * TAGS + n]);
        float G1 = __expf(emb[i1 * TAGS + n]);
        float G2 = __expf(emb[i2 * TAGS + n]);
        float G3 = __expf(emb[i3 * TAGS + n]);
        STEP(0, 1, E0, true);
        STEP(1, 0, E1, false);
        STEP(0, 1, E2, false);
        STEP(1, 0, E3, false);
        E0 = G0; E1 = G1; E2 = G2; E3 = G3;
    }
    // Tail (0-3 steps), rescale on the first.
    if (t < len) { STEP(0, 1, E0, true);  fb = 1; ++t; }
    if (t < len) { STEP(1, 0, E1, false); fb = 0; ++t; }
    if (t < len) { STEP(0, 1, E2, false); fb = 1; ++t; }

    // Finalize: out[b] = etot*ln2 + log( sum_n p[n] * exp(last[n]) )
    __syncthreads();
    float v = pbuf[fb][n] * __expf(last_t[n]);
#pragma unroll
    for (int sft = 16; sft > 0; sft >>= 1)
        v += __shfl_xor_sync(0xffffffffu, v, sft);
    if ((n & 31) == 0) wsum[n >> 5] = v;
    __syncthreads();
    if (n == 0)
        out[b] = (float)((double)etot * 0.6931471805599453 +
                         (double)__logf(wsum[0] + wsum[1] + wsum[2] + wsum[3]));
}

extern "C" void kernel_launch(void* const* d_in, const int* in_sizes, int n_in,
                              void* d_out, int out_size) {
    const float* em = (const float*)d_in[0];
    const int*   ts = (const int*)  d_in[1];
    const float* tr = (const float*)d_in[2];
    const float* hd = (const float*)d_in[3];
    const float* lt = (const float*)d_in[4];
    float* out = (float*)d_out;

    int B = in_sizes[1];                       // token_sizes count
    int T = in_sizes[0] / (B * TAGS);          // C == 1

    crf_logz_kernel<<<B, TAGS>>>(em, ts, tr, hd, lt, out, T);
}

// round 5
// speedup vs baseline: 1.7914x; 1.3733x over previous
#include <cuda_runtime.h>
#include <cuda_bf16.h>

#define TAGS 128
typedef __nv_bfloat162 bf2;

__global__ void __launch_bounds__(TAGS, 1) crf_logz_kernel(
    const float* __restrict__ emissions,     // [B, T, 1, TAGS]
    const int*   __restrict__ token_sizes,   // [B]
    const float* __restrict__ transitions,   // [1, 1, TAGS, TAGS]
    const float* __restrict__ head_t,        // [1, 1, TAGS]
    const float* __restrict__ last_t,        // [1, 1, TAGS]
    float*       __restrict__ out,           // [B, 1]
    int T)
{
    __shared__ __align__(16) __nv_bfloat16 pbuf[2][TAGS];
    __shared__ float wsum[4];

    const int n = threadIdx.x;      // output tag owned by this thread
    const int b = blockIdx.x;       // batch element owned by this CTA
    const int len = token_sizes[b];
    const float* emb = emissions + (size_t)b * T * TAGS;

    // exp(transitions) column n as bf16x2 pairs: T2[i] = (T[2i,n], T[2i+1,n]).
    bf2 T2[TAGS / 2];
#pragma unroll
    for (int i = 0; i < TAGS / 2; ++i)
        T2[i] = __floats2bfloat162_rn(__expf(transitions[(2 * i    ) * TAGS + n]),
                                      __expf(transitions[(2 * i + 1) * TAGS + n]));

    // alpha_0 = head + emissions[0]  ->  p = exp(alpha)  (bf16 storage)
    pbuf[0][n] = __float2bfloat16(__expf(head_t[n] + emb[n]));
    int etot = 0;        // exact integer sum of stripped binary exponents
    int fb = 0;          // live buffer for the tail bookkeeping

// One recurrence step, compile-time SRC/DST (static smem addressing).
// Matvec in bf16x2 HFMA2 (rt=2, no RF-bank penalty): 64 HFMA2 = 128 cyc pacing.
// Rescale by 2^{-exponent(p[0])} every step; bf16 range == fp32 range, so the
// p[0]-normalization that was safe in fp32 is safe here too.
#define STEP(SRC, DST, EV) do {                                            \
    __syncthreads();                                                       \
    unsigned short _cb = __bfloat16_as_ushort(pbuf[SRC][0]);               \
    int _e = (int)((_cb >> 7) & 255) - 127;                                \
    float _sc = __int_as_float((127 - _e) << 23);                          \
    bf2 _Es = __float2bfloat162_rn((EV) * _sc);                            \
    const uint4* _pd = reinterpret_cast<const uint4*>(&pbuf[SRC][0]);      \
    bf2 _h0 = __float2bfloat162_rn(0.0f);                                  \
    bf2 _h1 = _h0, _h2 = _h0, _h3 = _h0;                                   \
    _Pragma("unroll")                                                      \
    for (int _i = 0; _i < 16; ++_i) {                                      \
        uint4 _q = _pd[_i];                        /* 8 p-halves */        \
        _h0 = __hfma2(*reinterpret_cast<bf2*>(&_q.x), T2[4 * _i    ], _h0);\
        _h1 = __hfma2(*reinterpret_cast<bf2*>(&_q.y), T2[4 * _i + 1], _h1);\
        _h2 = __hfma2(*reinterpret_cast<bf2*>(&_q.z), T2[4 * _i + 2], _h2);\
        _h3 = __hfma2(*reinterpret_cast<bf2*>(&_q.w), T2[4 * _i + 3], _h3);\
    }                                                                      \
    bf2 _s = __hadd2(__hadd2(_h0, _h1), __hadd2(_h2, _h3));                \
    bf2 _t = __hadd2(_s, __lowhigh2highlow(_s));   /* lo+hi in both */     \
    bf2 _pn = __hmul2(_t, _Es);                                            \
    pbuf[DST][n] = __low2bfloat16(_pn);                                    \
    etot += _e;                                                            \
} while (0)

    // Main loop, groups of 4 steps; emissions exp()'d 4 steps (~900cyc) ahead.
    int t = 1;
    float E0 = __expf(emb[((1 < T) ? 1 : T - 1) * TAGS + n]);
    float E1 = __expf(emb[((2 < T) ? 2 : T - 1) * TAGS + n]);
    float E2 = __expf(emb[((3 < T) ? 3 : T - 1) * TAGS + n]);
    float E3 = __expf(emb[((4 < T) ? 4 : T - 1) * TAGS + n]);

    for (; t + 4 <= len; t += 4) {
        int tp = t + 4;
        int i0 = (tp     < T) ? tp     : T - 1;
        int i1 = (tp + 1 < T) ? tp + 1 : T - 1;
        int i2 = (tp + 2 < T) ? tp + 2 : T - 1;
        int i3 = (tp + 3 < T) ? tp + 3 : T - 1;
        float G0 = __expf(emb[i0 * TAGS + n]);
        float G1 = __expf(emb[i1 * TAGS + n]);
        float G2 = __expf(emb[i2 * TAGS + n]);
        float G3 = __expf(emb[i3 * TAGS + n]);
        STEP(0, 1, E0);
        STEP(1, 0, E1);
        STEP(0, 1, E2);
        STEP(1, 0, E3);
        E0 = G0; E1 = G1; E2 = G2; E3 = G3;
    }
    // Tail (0-3 steps).
    if (t < len) { STEP(0, 1, E0); fb = 1; ++t; }
    if (t < len) { STEP(1, 0, E1); fb = 0; ++t; }
    if (t < len) { STEP(0, 1, E2); fb = 1; ++t; }

    // Finalize: out[b] = etot*ln2 + log( sum_n p[n] * exp(last[n]) )  (fp32)
    __syncthreads();
    float v = __bfloat162float(pbuf[fb][n]) * __expf(last_t[n]);
#pragma unroll
    for (int sft = 16; sft > 0; sft >>= 1)
        v += __shfl_xor_sync(0xffffffffu, v, sft);
    if ((n & 31) == 0) wsum[n >> 5] = v;
    __syncthreads();
    if (n == 0)
        out[b] = (float)((double)etot * 0.6931471805599453 +
                         (double)__logf(wsum[0] + wsum[1] + wsum[2] + wsum[3]));
}

extern "C" void kernel_launch(void* const* d_in, const int* in_sizes, int n_in,
                              void* d_out, int out_size) {
    const float* em = (const float*)d_in[0];
    const int*   ts = (const int*)  d_in[1];
    const float* tr = (const float*)d_in[2];
    const float* hd = (const float*)d_in[3];
    const float* lt = (const float*)d_in[4];
    float* out = (float*)d_out;

    int B = in_sizes[1];                       // token_sizes count
    int T = in_sizes[0] / (B * TAGS);          // C == 1

    crf_logz_kernel<<<B, TAGS>>>(em, ts, tr, hd, lt, out, T);
}